// round 8
// baseline (speedup 1.0000x reference)
#include <cuda_runtime.h>
#include <cuda_bf16.h>
#include <cstdint>

#define FULL 0xFFFFFFFFu

namespace {
constexpr int BATCH = 256;
constexpr int MAXT  = 512;
constexpr int T1    = MAXT + 1;      // 513
constexpr int S     = 64;
constexpr int NPOS  = BATCH * T1;    // 131328
constexpr int TILE_M = 128;          // positions per phase-1 CTA
constexpr int NCTA1 = NPOS / TILE_M; // 1026 exact
constexpr int NBC   = 304;           // real logit columns
constexpr int PITCH = 72;            // bf16 row pitch (64 + 8 pad): conflict-free ldmatrix

// dynamic smem layout (bytes)
constexpr int SM_A     = 0;                       // union: A bf16 [128][72] / staging f32 [128][64]
constexpr int SM_B     = 32768;                   // W^T bf16 [304][72] = 43776
constexpr int SM_BIAS  = SM_B + 43776;            // 76544
constexpr int SM_ACT   = SM_BIAS + 1280;          // 77824
constexpr int SM_TOTAL = SM_ACT + 512;            // 78336
}

// Per position: 16 x float4 {ea, ebt, eot, est} = exp of {asel, beta, omb, start}.
__device__ float4 g_mid[NPOS * 16];
__device__ float  g_batch[BATCH];
__device__ int    g_done;            // zero-init; reset by winner each run
// Pre-transposed bf16 weight image W^T: [304 cols][72 pitch].
__device__ __align__(16) __nv_bfloat16 g_B[NBC * PITCH];
__device__ float g_bias[NBC];

// ---------------------------------------------------------------------------
// Baseline-PTX helpers (sm_80-level: compile fine for compute_100)
// ---------------------------------------------------------------------------
__device__ __forceinline__ uint32_t cvta_smem(const void* p) {
    uint32_t a;
    asm("{ .reg .u64 t; cvta.to.shared.u64 t, %1; cvt.u32.u64 %0, t; }" : "=r"(a) : "l"(p));
    return a;
}
__device__ __forceinline__ void ldsm4(uint32_t* r, uint32_t addr) {
    asm volatile("ldmatrix.sync.aligned.m8n8.x4.shared.b16 {%0,%1,%2,%3}, [%4];"
                 : "=r"(r[0]), "=r"(r[1]), "=r"(r[2]), "=r"(r[3]) : "r"(addr));
}
__device__ __forceinline__ void mma16816(float* d, const uint32_t* a, const uint32_t* b) {
    asm volatile("mma.sync.aligned.m16n8k16.row.col.f32.bf16.bf16.f32 "
                 "{%0,%1,%2,%3}, {%4,%5,%6,%7}, {%8,%9}, {%0,%1,%2,%3};"
                 : "+f"(d[0]), "+f"(d[1]), "+f"(d[2]), "+f"(d[3])
                 : "r"(a[0]), "r"(a[1]), "r"(a[2]), "r"(a[3]), "r"(b[0]), "r"(b[1]));
}
__device__ __forceinline__ float frcp(float x) {
    float r;
    asm("rcp.approx.ftz.f32 %0, %1;" : "=f"(r) : "f"(x));
    return r;
}

// ---------------------------------------------------------------------------
// Prep: W^T bf16 image [304][72] + bias vector. 76 x 256 threads.
// ---------------------------------------------------------------------------
__global__ void prep_kernel(
    const float* __restrict__ Wa, const float* __restrict__ ba,
    const float* __restrict__ Ws, const float* __restrict__ bs,
    const float* __restrict__ Wst, const float* __restrict__ bst)
{
    int idx = blockIdx.x * blockDim.x + threadIdx.x;    // 0..19455
    if (idx < NBC) {
        float bv;
        if (idx < 256)      bv = __ldg(&ba[idx]);
        else if (idx < 288) bv = __ldg(&bs[idx - 256]);
        else                bv = __ldg(&bst[idx - 288]);
        g_bias[idx] = bv;
    }
    if (idx >= NBC * S) return;
    int n = idx >> 6, k = idx & 63;
    float w;
    if (n < 256)      w = __ldg(&Wa[k * 256 + n]);
    else if (n < 288) w = __ldg(&Ws[k * 32 + (n - 256)]);
    else              w = __ldg(&Wst[k * 16 + (n - 288)]);
    g_B[n * PITCH + k] = __float2bfloat16(w);
}

// ---------------------------------------------------------------------------
// Phase 1: bf16 HMMA GEMM (128 pos x 304 cols, K=64) + fused softmax epilogue
// that stores PROBABILITIES (exp of the log values) for phase 2.
// ---------------------------------------------------------------------------
__global__ __launch_bounds__(256, 2) void phase1_kernel(
    const float* __restrict__ s_i,
    const int*   __restrict__ actions,
    const int*   __restrict__ lengths)
{
    extern __shared__ __align__(16) unsigned char smem[];
    const int tid  = threadIdx.x;
    const int pos0 = blockIdx.x * TILE_M;

    int need = 0;
    if (tid < TILE_M) {
        int pos = pos0 + tid;
        int b = pos / T1;
        int t = pos - b * T1;
        need = (t <= __ldg(&lengths[b]));
        ((int*)(smem + SM_ACT))[tid] = (t < MAXT) ? __ldg(&actions[b * MAXT + t]) : 0;
    }
    if (!__syncthreads_or(need)) return;

    // --- stage B ---
    {
        const uint4* src = (const uint4*)g_B;
        uint4* dst = (uint4*)(smem + SM_B);
        #pragma unroll
        for (int i = tid; i < NBC * PITCH * 2 / 16; i += 256) dst[i] = __ldg(&src[i]);
    }
    // --- stage bias ---
    {
        float* dst = (float*)(smem + SM_BIAS);
        for (int i = tid; i < NBC; i += 256) dst[i] = g_bias[i];
    }
    // --- stage A: fp32 -> bf16, [128][72] pitch ---
    {
        const float2* src = (const float2*)(s_i + (size_t)pos0 * S);
        __nv_bfloat16* A = (__nv_bfloat16*)(smem + SM_A);
        #pragma unroll
        for (int i = tid; i < TILE_M * (S / 2); i += 256) {
            int row = i >> 5, cp = i & 31;
            float2 v = __ldg(&src[i]);
            __nv_bfloat162 h = __floats2bfloat162_rn(v.x, v.y);
            *(uint32_t*)(A + row * PITCH + 2 * cp) = *(uint32_t*)&h;
        }
    }
    __syncthreads();

    const int wid = tid >> 5, lane = tid & 31;
    const int g = lane >> 2, tig = lane & 3;
    const int m0 = wid * 16;
    const uint32_t sb = cvta_smem(smem);

    // --- A fragments ---
    uint32_t afrag[4][4];
    {
        int r  = m0 + (lane & 7) + ((lane >> 3) & 1) * 8;
        int kc = ((lane >> 4) & 1) * 8;
        uint32_t base = sb + SM_A + (uint32_t)(r * PITCH + kc) * 2;
        #pragma unroll
        for (int s = 0; s < 4; s++) ldsm4(afrag[s], base + s * 32);
    }
    const int act_lo = ((const int*)(smem + SM_ACT))[m0 + g];
    const int act_hi = ((const int*)(smem + SM_ACT))[m0 + g + 8];
    __syncthreads();   // A smem region becomes the f32 staging buffer

    float* sh_out = (float*)(smem + SM_A);              // [128][64]
    const float* biasS = (const float*)(smem + SM_BIAS);
    const int row_lo = m0 + g, row_hi = m0 + g + 8;

    #pragma unroll 1
    for (int c = 0; c < 19; c++) {
        const int n0 = c * 16;

        uint32_t bfrag[2][4][2];
        #pragma unroll
        for (int f = 0; f < 2; f++) {
            int n = n0 + f * 8 + (lane & 7);
            uint32_t base = sb + SM_B + (uint32_t)n * (PITCH * 2) + ((lane >> 3) & 3) * 16;
            uint32_t r[4];
            ldsm4(r, base);
            bfrag[f][0][0] = r[0]; bfrag[f][0][1] = r[1];
            bfrag[f][1][0] = r[2]; bfrag[f][1][1] = r[3];
            ldsm4(r, base + 64);
            bfrag[f][2][0] = r[0]; bfrag[f][2][1] = r[1];
            bfrag[f][3][0] = r[2]; bfrag[f][3][1] = r[3];
        }

        float acc0[4] = {0.f, 0.f, 0.f, 0.f};
        float acc1[4] = {0.f, 0.f, 0.f, 0.f};
        #pragma unroll
        for (int s = 0; s < 4; s++) {
            mma16816(acc0, afrag[s], bfrag[0][s]);
            mma16816(acc1, afrag[s], bfrag[1][s]);
        }

        float2 bv0 = *(const float2*)&biasS[n0 + 2 * tig];
        float2 bv1 = *(const float2*)&biasS[n0 + 8 + 2 * tig];
        float zl0 = acc0[0] + bv0.x, zl1 = acc0[1] + bv0.y;
        float zl2 = acc1[0] + bv1.x, zl3 = acc1[1] + bv1.y;
        float zh0 = acc0[2] + bv0.x, zh1 = acc0[3] + bv0.y;
        float zh2 = acc1[2] + bv1.x, zh3 = acc1[3] + bv1.y;

        // exps (used by every branch)
        float xl0 = __expf(zl0), xl1 = __expf(zl1), xl2 = __expf(zl2), xl3 = __expf(zl3);
        float xh0 = __expf(zh0), xh1 = __expf(zh1), xh2 = __expf(zh2), xh3 = __expf(zh3);

        if (c < 16) {
            // ---- action block c: P(sel) = exp(zsel)/sum over 16 ----
            int c0 = 2 * tig, c1 = c0 + 1, c2 = c0 + 8, c3 = c1 + 8;
            float el = (xl0 + xl1) + (xl2 + xl3);
            float eh = (xh0 + xh1) + (xh2 + xh3);
            float sl = (c0 == act_lo ? xl0 : 0.f) + (c1 == act_lo ? xl1 : 0.f)
                     + (c2 == act_lo ? xl2 : 0.f) + (c3 == act_lo ? xl3 : 0.f);
            float sh = (c0 == act_hi ? xh0 : 0.f) + (c1 == act_hi ? xh1 : 0.f)
                     + (c2 == act_hi ? xh2 : 0.f) + (c3 == act_hi ? xh3 : 0.f);
            el += __shfl_xor_sync(FULL, el, 1); el += __shfl_xor_sync(FULL, el, 2);
            eh += __shfl_xor_sync(FULL, eh, 1); eh += __shfl_xor_sync(FULL, eh, 2);
            sl += __shfl_xor_sync(FULL, sl, 1); sl += __shfl_xor_sync(FULL, sl, 2);
            sh += __shfl_xor_sync(FULL, sh, 1); sh += __shfl_xor_sync(FULL, sh, 2);
            if (tig == 0) {
                sh_out[row_lo * 64 + c * 4] = sl * frcp(el);   // ea
                sh_out[row_hi * 64 + c * 4] = sh * frcp(eh);
            }
        } else if (c < 18) {
            // ---- stop pairs: store stop/continue probabilities ----
            int jb0 = (n0 - 256) / 2 + tig;
            int jb1 = jb0 + 4;
            float r;
            r = frcp(xl0 + xl1);
            sh_out[row_lo * 64 + jb0 * 4 + 1] = xl0 * r;       // ebt
            sh_out[row_lo * 64 + jb0 * 4 + 2] = xl1 * r;       // eot
            r = frcp(xl2 + xl3);
            sh_out[row_lo * 64 + jb1 * 4 + 1] = xl2 * r;
            sh_out[row_lo * 64 + jb1 * 4 + 2] = xl3 * r;
            r = frcp(xh0 + xh1);
            sh_out[row_hi * 64 + jb0 * 4 + 1] = xh0 * r;
            sh_out[row_hi * 64 + jb0 * 4 + 2] = xh1 * r;
            r = frcp(xh2 + xh3);
            sh_out[row_hi * 64 + jb1 * 4 + 1] = xh2 * r;
            sh_out[row_hi * 64 + jb1 * 4 + 2] = xh3 * r;
        } else {
            // ---- start: probabilities over 16 ----
            float el = (xl0 + xl1) + (xl2 + xl3);
            float eh = (xh0 + xh1) + (xh2 + xh3);
            el += __shfl_xor_sync(FULL, el, 1); el += __shfl_xor_sync(FULL, el, 2);
            eh += __shfl_xor_sync(FULL, eh, 1); eh += __shfl_xor_sync(FULL, eh, 2);
            float rl = frcp(el), rh = frcp(eh);
            int c0 = 2 * tig, c2 = c0 + 8;
            sh_out[row_lo * 64 + c0 * 4 + 3]       = xl0 * rl;  // est
            sh_out[row_lo * 64 + (c0 + 1) * 4 + 3] = xl1 * rl;
            sh_out[row_lo * 64 + c2 * 4 + 3]       = xl2 * rl;
            sh_out[row_lo * 64 + (c2 + 1) * 4 + 3] = xl3 * rl;
            sh_out[row_hi * 64 + c0 * 4 + 3]       = xh0 * rh;
            sh_out[row_hi * 64 + (c0 + 1) * 4 + 3] = xh1 * rh;
            sh_out[row_hi * 64 + c2 * 4 + 3]       = xh2 * rh;
            sh_out[row_hi * 64 + (c2 + 1) * 4 + 3] = xh3 * rh;
        }
    }

    // Per-warp flush of its own 16 rows.
    {
        float4* dst = g_mid + (size_t)(pos0 + m0) * 16;
        const float4* src = (const float4*)(sh_out + m0 * 64);
        #pragma unroll
        for (int i = lane; i < 256; i += 32) dst[i] = src[i];
    }
}

// ---------------------------------------------------------------------------
// Phase 2: prob-domain recursion. 4 lanes/chain x 4 states/lane, 8 chains/warp.
//   P' = (ea*r) * fma(s, est, P*eot),  s = sum_k P_k*ebt_k
// Renorm scale r = rcp(sum P') applied one step late; C accumulates log of
// applied scales off-chain. ALL intra-chain shfls use the QUAD mask — chains
// in one warp have different L, so FULL-mask shfl inside the loop deadlocks.
// Last block reduces g_batch in fixed order (deterministic) and writes out.
// ---------------------------------------------------------------------------
__global__ __launch_bounds__(32) void phase2_kernel(const int* __restrict__ lengths,
                                                    float* __restrict__ out)
{
    const int lane = threadIdx.x;
    const int q    = lane >> 2;               // chain within warp (0..7)
    const int sub  = lane & 3;                // 4 states per lane
    const int b    = blockIdx.x * 8 + q;
    const unsigned qm = 0xFu << (q * 4);      // quad member mask (same L per quad)

    const float4* base = g_mid + (size_t)b * T1 * 16 + sub * 4;
    const int L = __ldg(&lengths[b]);         // 1..512

    float4 w0 = base[0], w1 = base[1], w2 = base[2], w3 = base[3];
    float P0 = w0.w * w0.x;                   // est0 * ea0
    float P1 = w1.w * w1.x;
    float P2 = w2.w * w2.x;
    float P3 = w3.w * w3.x;

    // Prefetch ring: buf[u] holds step (t) with t ≡ 1+u when consumed.
    float4 buf[4][4];
    #pragma unroll
    for (int s = 0; s < 4; s++) {
        const float4* p = base + (size_t)(1 + s) * 16;   // rows 1..4 always exist
        buf[s][0] = p[0]; buf[s][1] = p[1]; buf[s][2] = p[2]; buf[s][3] = p[3];
    }

    float r = 1.f, C = 0.f, pend = 0.f;
    int t = 1;
    while (t < L) {
        #pragma unroll
        for (int u = 0; u < 4; u++) {
            if (t < L) {
                float4 va = buf[u][0], vb = buf[u][1], vc = buf[u][2], vd = buf[u][3];
                int tf = t + 4; if (tf > MAXT) tf = MAXT;
                const float4* p = base + (size_t)tf * 16;
                buf[u][0] = p[0]; buf[u][1] = p[1]; buf[u][2] = p[2]; buf[u][3] = p[3];

                C += pend;
                // s = sum_k P*ebt  (chain: mul + tree + 2 quad shfl)
                float s = (P0 * va.y + P1 * vb.y) + (P2 * vc.y + P3 * vd.y);
                s += __shfl_xor_sync(qm, s, 1);
                s += __shfl_xor_sync(qm, s, 2);
                // ea*r off-chain
                float e0 = va.x * r, e1 = vb.x * r, e2 = vc.x * r, e3 = vd.x * r;
                P0 = e0 * fmaf(s, va.w, P0 * va.z);
                P1 = e1 * fmaf(s, vb.w, P1 * vb.z);
                P2 = e2 * fmaf(s, vc.w, P2 * vc.z);
                P3 = e3 * fmaf(s, vd.w, P3 * vd.z);
                // side chain: next renorm scale + its log (applied next iter)
                float uS = (P0 + P1) + (P2 + P3);
                uS += __shfl_xor_sync(qm, uS, 1);
                uS += __shfl_xor_sync(qm, uS, 2);
                pend = __logf(uS);
                r = frcp(uS);
                t++;
            }
        }
    }

    // Final: ans = C + log(sum_k P*ebt at row L)  (last scale never applied)
    {
        const float4* p = base + (size_t)L * 16;
        float4 va = p[0], vb = p[1], vc = p[2], vd = p[3];
        float s = (P0 * va.y + P1 * vb.y) + (P2 * vc.y + P3 * vd.y);
        s += __shfl_xor_sync(qm, s, 1);
        s += __shfl_xor_sync(qm, s, 2);
        if (sub == 0) g_batch[b] = C + __logf(s);
    }

    // Deterministic last-block reduction (warp-uniform from here).
    __syncwarp();
    __threadfence();
    int ticket = 0;
    if (lane == 0) ticket = atomicAdd(&g_done, 1);
    ticket = __shfl_sync(FULL, ticket, 0);
    if (ticket == gridDim.x - 1) {
        __threadfence();
        float a = 0.f;
        #pragma unroll
        for (int i = 0; i < 8; i++) a += g_batch[lane * 8 + i];  // fixed order
        #pragma unroll
        for (int d = 16; d; d >>= 1) a += __shfl_xor_sync(FULL, a, d);
        if (lane == 0) { out[0] = -a; g_done = 0; }
    }
}

// ---------------------------------------------------------------------------
// d_in order: s_i_batch, actions_batch, lengths, W_action, b_action,
//             W_stop, b_stop, W_start, b_start
// ---------------------------------------------------------------------------
extern "C" void kernel_launch(void* const* d_in, const int* in_sizes, int n_in,
                              void* d_out, int out_size)
{
    (void)in_sizes; (void)n_in; (void)out_size;
    const float* s_i     = (const float*)d_in[0];
    const int*   actions = (const int*)d_in[1];
    const int*   lengths = (const int*)d_in[2];
    const float* Wa      = (const float*)d_in[3];
    const float* ba      = (const float*)d_in[4];
    const float* Ws      = (const float*)d_in[5];
    const float* bs      = (const float*)d_in[6];
    const float* Wst     = (const float*)d_in[7];
    const float* bst     = (const float*)d_in[8];

    static bool attr_set = false;
    if (!attr_set) {
        cudaFuncSetAttribute(phase1_kernel,
                             cudaFuncAttributeMaxDynamicSharedMemorySize, SM_TOTAL);
        attr_set = true;
    }

    prep_kernel<<<76, 256>>>(Wa, ba, Ws, bs, Wst, bst);
    phase1_kernel<<<NCTA1, 256, SM_TOTAL>>>(s_i, actions, lengths);
    phase2_kernel<<<32, 32>>>(lengths, (float*)d_out);
}

// round 9
// speedup vs baseline: 2.7885x; 2.7885x over previous
#include <cuda_runtime.h>
#include <cuda_bf16.h>
#include <cstdint>

#define FULL 0xFFFFFFFFu

namespace {
constexpr int BATCH = 256;
constexpr int MAXT  = 512;
constexpr int T1    = MAXT + 1;      // 513
constexpr int S     = 64;
constexpr int NPOS  = BATCH * T1;    // 131328
constexpr int TILE_M = 128;          // positions per phase-1 CTA
constexpr int NCTA1 = NPOS / TILE_M; // 1026 exact
constexpr int NBC   = 304;           // real logit columns
constexpr int PITCH = 72;            // bf16 row pitch (64 + 8 pad): conflict-free ldmatrix

// dynamic smem layout (bytes)
constexpr int SM_A     = 0;                       // union: A bf16 [128][72] / staging f32 [128][64]
constexpr int SM_B     = 32768;                   // W^T bf16 [304][72] = 43776
constexpr int SM_BIAS  = SM_B + 43776;            // 76544
constexpr int SM_ACT   = SM_BIAS + 1280;          // 77824
constexpr int SM_TOTAL = SM_ACT + 512;            // 78336
}

// Per position: 16 x float4 {ea, ebt, eot, est} = exp of {asel, beta, omb, start}.
__device__ float4 g_mid[NPOS * 16];
__device__ float  g_batch[BATCH];
__device__ int    g_done;            // zero-init; reset by winner each run
// Pre-transposed bf16 weight image W^T: [304 cols][72 pitch].
__device__ __align__(16) __nv_bfloat16 g_B[NBC * PITCH];
__device__ float g_bias[NBC];

// ---------------------------------------------------------------------------
// Baseline-PTX helpers (sm_80-level: compile fine for compute_100)
// ---------------------------------------------------------------------------
__device__ __forceinline__ uint32_t cvta_smem(const void* p) {
    uint32_t a;
    asm("{ .reg .u64 t; cvta.to.shared.u64 t, %1; cvt.u32.u64 %0, t; }" : "=r"(a) : "l"(p));
    return a;
}
__device__ __forceinline__ void ldsm4(uint32_t* r, uint32_t addr) {
    asm volatile("ldmatrix.sync.aligned.m8n8.x4.shared.b16 {%0,%1,%2,%3}, [%4];"
                 : "=r"(r[0]), "=r"(r[1]), "=r"(r[2]), "=r"(r[3]) : "r"(addr));
}
__device__ __forceinline__ void mma16816(float* d, const uint32_t* a, const uint32_t* b) {
    asm volatile("mma.sync.aligned.m16n8k16.row.col.f32.bf16.bf16.f32 "
                 "{%0,%1,%2,%3}, {%4,%5,%6,%7}, {%8,%9}, {%0,%1,%2,%3};"
                 : "+f"(d[0]), "+f"(d[1]), "+f"(d[2]), "+f"(d[3])
                 : "r"(a[0]), "r"(a[1]), "r"(a[2]), "r"(a[3]), "r"(b[0]), "r"(b[1]));
}
__device__ __forceinline__ float frcp(float x) {
    float r;
    asm("rcp.approx.ftz.f32 %0, %1;" : "=f"(r) : "f"(x));
    return r;
}

// ---------------------------------------------------------------------------
// Prep: W^T bf16 image [304][72] + bias vector. 76 x 256 threads.
// ---------------------------------------------------------------------------
__global__ void prep_kernel(
    const float* __restrict__ Wa, const float* __restrict__ ba,
    const float* __restrict__ Ws, const float* __restrict__ bs,
    const float* __restrict__ Wst, const float* __restrict__ bst)
{
    int idx = blockIdx.x * blockDim.x + threadIdx.x;    // 0..19455
    if (idx < NBC) {
        float bv;
        if (idx < 256)      bv = __ldg(&ba[idx]);
        else if (idx < 288) bv = __ldg(&bs[idx - 256]);
        else                bv = __ldg(&bst[idx - 288]);
        g_bias[idx] = bv;
    }
    if (idx >= NBC * S) return;
    int n = idx >> 6, k = idx & 63;
    float w;
    if (n < 256)      w = __ldg(&Wa[k * 256 + n]);
    else if (n < 288) w = __ldg(&Ws[k * 32 + (n - 256)]);
    else              w = __ldg(&Wst[k * 16 + (n - 288)]);
    g_B[n * PITCH + k] = __float2bfloat16(w);
}

// ---------------------------------------------------------------------------
// Phase 1: bf16 HMMA GEMM (128 pos x 304 cols, K=64) + fused softmax epilogue
// that stores PROBABILITIES (exp of the log values) for phase 2.
// ---------------------------------------------------------------------------
__global__ __launch_bounds__(256, 2) void phase1_kernel(
    const float* __restrict__ s_i,
    const int*   __restrict__ actions,
    const int*   __restrict__ lengths)
{
    extern __shared__ __align__(16) unsigned char smem[];
    const int tid  = threadIdx.x;
    const int pos0 = blockIdx.x * TILE_M;

    int need = 0;
    if (tid < TILE_M) {
        int pos = pos0 + tid;
        int b = pos / T1;
        int t = pos - b * T1;
        need = (t <= __ldg(&lengths[b]));
        ((int*)(smem + SM_ACT))[tid] = (t < MAXT) ? __ldg(&actions[b * MAXT + t]) : 0;
    }
    if (!__syncthreads_or(need)) return;

    // --- stage B ---
    {
        const uint4* src = (const uint4*)g_B;
        uint4* dst = (uint4*)(smem + SM_B);
        #pragma unroll
        for (int i = tid; i < NBC * PITCH * 2 / 16; i += 256) dst[i] = __ldg(&src[i]);
    }
    // --- stage bias ---
    {
        float* dst = (float*)(smem + SM_BIAS);
        for (int i = tid; i < NBC; i += 256) dst[i] = g_bias[i];
    }
    // --- stage A: fp32 -> bf16, [128][72] pitch ---
    {
        const float2* src = (const float2*)(s_i + (size_t)pos0 * S);
        __nv_bfloat16* A = (__nv_bfloat16*)(smem + SM_A);
        #pragma unroll
        for (int i = tid; i < TILE_M * (S / 2); i += 256) {
            int row = i >> 5, cp = i & 31;
            float2 v = __ldg(&src[i]);
            __nv_bfloat162 h = __floats2bfloat162_rn(v.x, v.y);
            *(uint32_t*)(A + row * PITCH + 2 * cp) = *(uint32_t*)&h;
        }
    }
    __syncthreads();

    const int wid = tid >> 5, lane = tid & 31;
    const int g = lane >> 2, tig = lane & 3;
    const int m0 = wid * 16;
    const uint32_t sb = cvta_smem(smem);

    // --- A fragments ---
    uint32_t afrag[4][4];
    {
        int r  = m0 + (lane & 7) + ((lane >> 3) & 1) * 8;
        int kc = ((lane >> 4) & 1) * 8;
        uint32_t base = sb + SM_A + (uint32_t)(r * PITCH + kc) * 2;
        #pragma unroll
        for (int s = 0; s < 4; s++) ldsm4(afrag[s], base + s * 32);
    }
    const int act_lo = ((const int*)(smem + SM_ACT))[m0 + g];
    const int act_hi = ((const int*)(smem + SM_ACT))[m0 + g + 8];
    __syncthreads();   // A smem region becomes the f32 staging buffer

    float* sh_out = (float*)(smem + SM_A);              // [128][64]
    const float* biasS = (const float*)(smem + SM_BIAS);
    const int row_lo = m0 + g, row_hi = m0 + g + 8;

    #pragma unroll 1
    for (int c = 0; c < 19; c++) {
        const int n0 = c * 16;

        uint32_t bfrag[2][4][2];
        #pragma unroll
        for (int f = 0; f < 2; f++) {
            int n = n0 + f * 8 + (lane & 7);
            uint32_t base = sb + SM_B + (uint32_t)n * (PITCH * 2) + ((lane >> 3) & 3) * 16;
            uint32_t r[4];
            ldsm4(r, base);
            bfrag[f][0][0] = r[0]; bfrag[f][0][1] = r[1];
            bfrag[f][1][0] = r[2]; bfrag[f][1][1] = r[3];
            ldsm4(r, base + 64);
            bfrag[f][2][0] = r[0]; bfrag[f][2][1] = r[1];
            bfrag[f][3][0] = r[2]; bfrag[f][3][1] = r[3];
        }

        float acc0[4] = {0.f, 0.f, 0.f, 0.f};
        float acc1[4] = {0.f, 0.f, 0.f, 0.f};
        #pragma unroll
        for (int s = 0; s < 4; s++) {
            mma16816(acc0, afrag[s], bfrag[0][s]);
            mma16816(acc1, afrag[s], bfrag[1][s]);
        }

        float2 bv0 = *(const float2*)&biasS[n0 + 2 * tig];
        float2 bv1 = *(const float2*)&biasS[n0 + 8 + 2 * tig];
        float zl0 = acc0[0] + bv0.x, zl1 = acc0[1] + bv0.y;
        float zl2 = acc1[0] + bv1.x, zl3 = acc1[1] + bv1.y;
        float zh0 = acc0[2] + bv0.x, zh1 = acc0[3] + bv0.y;
        float zh2 = acc1[2] + bv1.x, zh3 = acc1[3] + bv1.y;

        // exps (used by every branch)
        float xl0 = __expf(zl0), xl1 = __expf(zl1), xl2 = __expf(zl2), xl3 = __expf(zl3);
        float xh0 = __expf(zh0), xh1 = __expf(zh1), xh2 = __expf(zh2), xh3 = __expf(zh3);

        if (c < 16) {
            // ---- action block c: P(sel) = exp(zsel)/sum over 16 ----
            int c0 = 2 * tig, c1 = c0 + 1, c2 = c0 + 8, c3 = c1 + 8;
            float el = (xl0 + xl1) + (xl2 + xl3);
            float eh = (xh0 + xh1) + (xh2 + xh3);
            float sl = (c0 == act_lo ? xl0 : 0.f) + (c1 == act_lo ? xl1 : 0.f)
                     + (c2 == act_lo ? xl2 : 0.f) + (c3 == act_lo ? xl3 : 0.f);
            float sh = (c0 == act_hi ? xh0 : 0.f) + (c1 == act_hi ? xh1 : 0.f)
                     + (c2 == act_hi ? xh2 : 0.f) + (c3 == act_hi ? xh3 : 0.f);
            el += __shfl_xor_sync(FULL, el, 1); el += __shfl_xor_sync(FULL, el, 2);
            eh += __shfl_xor_sync(FULL, eh, 1); eh += __shfl_xor_sync(FULL, eh, 2);
            sl += __shfl_xor_sync(FULL, sl, 1); sl += __shfl_xor_sync(FULL, sl, 2);
            sh += __shfl_xor_sync(FULL, sh, 1); sh += __shfl_xor_sync(FULL, sh, 2);
            if (tig == 0) {
                sh_out[row_lo * 64 + c * 4] = sl * frcp(el);   // ea
                sh_out[row_hi * 64 + c * 4] = sh * frcp(eh);
            }
        } else if (c < 18) {
            // ---- stop pairs: store stop/continue probabilities ----
            int jb0 = (n0 - 256) / 2 + tig;
            int jb1 = jb0 + 4;
            float r;
            r = frcp(xl0 + xl1);
            sh_out[row_lo * 64 + jb0 * 4 + 1] = xl0 * r;       // ebt
            sh_out[row_lo * 64 + jb0 * 4 + 2] = xl1 * r;       // eot
            r = frcp(xl2 + xl3);
            sh_out[row_lo * 64 + jb1 * 4 + 1] = xl2 * r;
            sh_out[row_lo * 64 + jb1 * 4 + 2] = xl3 * r;
            r = frcp(xh0 + xh1);
            sh_out[row_hi * 64 + jb0 * 4 + 1] = xh0 * r;
            sh_out[row_hi * 64 + jb0 * 4 + 2] = xh1 * r;
            r = frcp(xh2 + xh3);
            sh_out[row_hi * 64 + jb1 * 4 + 1] = xh2 * r;
            sh_out[row_hi * 64 + jb1 * 4 + 2] = xh3 * r;
        } else {
            // ---- start: probabilities over 16 ----
            float el = (xl0 + xl1) + (xl2 + xl3);
            float eh = (xh0 + xh1) + (xh2 + xh3);
            el += __shfl_xor_sync(FULL, el, 1); el += __shfl_xor_sync(FULL, el, 2);
            eh += __shfl_xor_sync(FULL, eh, 1); eh += __shfl_xor_sync(FULL, eh, 2);
            float rl = frcp(el), rh = frcp(eh);
            int c0 = 2 * tig, c2 = c0 + 8;
            sh_out[row_lo * 64 + c0 * 4 + 3]       = xl0 * rl;  // est
            sh_out[row_lo * 64 + (c0 + 1) * 4 + 3] = xl1 * rl;
            sh_out[row_lo * 64 + c2 * 4 + 3]       = xl2 * rl;
            sh_out[row_lo * 64 + (c2 + 1) * 4 + 3] = xl3 * rl;
            sh_out[row_hi * 64 + c0 * 4 + 3]       = xh0 * rh;
            sh_out[row_hi * 64 + (c0 + 1) * 4 + 3] = xh1 * rh;
            sh_out[row_hi * 64 + c2 * 4 + 3]       = xh2 * rh;
            sh_out[row_hi * 64 + (c2 + 1) * 4 + 3] = xh3 * rh;
        }
    }

    // Per-warp flush of its own 16 rows.
    {
        float4* dst = g_mid + (size_t)(pos0 + m0) * 16;
        const float4* src = (const float4*)(sh_out + m0 * 64);
        #pragma unroll
        for (int i = lane; i < 256; i += 32) dst[i] = src[i];
    }
}

// ---------------------------------------------------------------------------
// Phase 2: prob-domain recursion, ONE WARP PER BATCH (L warp-uniform → no
// divergence; FULL-mask shfls legal; main loop unguarded 8-step blocks).
// Lanes 0..15 hold the 16 states (16..31 mirror). Per step:
//   s  = sum_k P_k * ebt_k                       (4 shfls, on chain)
//   P' = (ea * r) * fma(s, est, P * eot)         (r = lagged frcp(s_prev))
//   C += log(s_prev)  [lagged, off-chain]
// Invariant: TrueF_t = P_t * exp(C_t). Final: C + log(sum P*ebt at row L).
// 8-deep prefetch ring (1 float4/lane) hides ~900+ cycles of load latency.
// Last block (ticket) reduces g_batch in fixed order and writes out.
// ---------------------------------------------------------------------------
__global__ __launch_bounds__(32) void phase2_kernel(const int* __restrict__ lengths,
                                                    float* __restrict__ out)
{
    const int lane = threadIdx.x;
    const int j    = lane & 15;
    const int b    = blockIdx.x;

    const float4* base = g_mid + (size_t)b * T1 * 16 + j;
    const int L = __ldg(&lengths[b]);         // 1..512, warp-uniform

    float4 w0 = base[0];
    float P = w0.w * w0.x;                    // est0 * ea0

    // Prefetch ring, depth 8: rows 1..8 always exist (T1 = 513).
    float4 buf[8];
    #pragma unroll
    for (int s = 0; s < 8; s++) buf[s] = base[(size_t)(1 + s) * 16];

    float r = 1.f, C = 0.f, pend = 0.f;
    int t = 1;
    const int nsteps = L - 1;
    const int nfull  = nsteps >> 3;

    for (int blk = 0; blk < nfull; blk++) {
        #pragma unroll
        for (int u = 0; u < 8; u++) {
            float4 v = buf[u];
            int tf = t + 8; if (tf > MAXT) tf = MAXT;
            buf[u] = base[(size_t)tf * 16];

            C += pend;
            float s = P * v.y;
            s += __shfl_xor_sync(FULL, s, 1);
            s += __shfl_xor_sync(FULL, s, 2);
            s += __shfl_xor_sync(FULL, s, 4);
            s += __shfl_xor_sync(FULL, s, 8);
            float e = v.x * r;                // lagged renorm, off chain
            P = e * fmaf(s, v.w, P * v.z);
            pend = __logf(s);                 // off chain (consumed next step)
            r = frcp(s);                      // off chain (consumed next step)
            t++;
        }
    }
    // Remainder (0..7 steps, warp-uniform branch).
    for (int u = 0; u < (nsteps & 7); u++) {
        float4 v = buf[u];
        C += pend;
        float s = P * v.y;
        s += __shfl_xor_sync(FULL, s, 1);
        s += __shfl_xor_sync(FULL, s, 2);
        s += __shfl_xor_sync(FULL, s, 4);
        s += __shfl_xor_sync(FULL, s, 8);
        float e = v.x * r;
        P = e * fmaf(s, v.w, P * v.z);
        pend = __logf(s);
        r = frcp(s);
        t++;
    }

    // Final: ans = C + log(sum_k P*ebt at row L). (pend/r of last step unused.)
    {
        float4 vL = base[(size_t)L * 16];
        float s = P * vL.y;
        s += __shfl_xor_sync(FULL, s, 1);
        s += __shfl_xor_sync(FULL, s, 2);
        s += __shfl_xor_sync(FULL, s, 4);
        s += __shfl_xor_sync(FULL, s, 8);
        if (lane == 0) g_batch[b] = C + __logf(s);
    }

    // Deterministic last-block reduction (warp-uniform).
    __syncwarp();
    __threadfence();
    int ticket = 0;
    if (lane == 0) ticket = atomicAdd(&g_done, 1);
    ticket = __shfl_sync(FULL, ticket, 0);
    if (ticket == gridDim.x - 1) {
        __threadfence();
        float a = 0.f;
        #pragma unroll
        for (int i = 0; i < 8; i++) a += g_batch[lane * 8 + i];  // fixed order
        #pragma unroll
        for (int d = 16; d; d >>= 1) a += __shfl_xor_sync(FULL, a, d);
        if (lane == 0) { out[0] = -a; g_done = 0; }
    }
}

// ---------------------------------------------------------------------------
// d_in order: s_i_batch, actions_batch, lengths, W_action, b_action,
//             W_stop, b_stop, W_start, b_start
// ---------------------------------------------------------------------------
extern "C" void kernel_launch(void* const* d_in, const int* in_sizes, int n_in,
                              void* d_out, int out_size)
{
    (void)in_sizes; (void)n_in; (void)out_size;
    const float* s_i     = (const float*)d_in[0];
    const int*   actions = (const int*)d_in[1];
    const int*   lengths = (const int*)d_in[2];
    const float* Wa      = (const float*)d_in[3];
    const float* ba      = (const float*)d_in[4];
    const float* Ws      = (const float*)d_in[5];
    const float* bs      = (const float*)d_in[6];
    const float* Wst     = (const float*)d_in[7];
    const float* bst     = (const float*)d_in[8];

    static bool attr_set = false;
    if (!attr_set) {
        cudaFuncSetAttribute(phase1_kernel,
                             cudaFuncAttributeMaxDynamicSharedMemorySize, SM_TOTAL);
        attr_set = true;
    }

    prep_kernel<<<76, 256>>>(Wa, ba, Ws, bs, Wst, bst);
    phase1_kernel<<<NCTA1, 256, SM_TOTAL>>>(s_i, actions, lengths);
    phase2_kernel<<<BATCH, 32>>>(lengths, (float*)d_out);
}